// round 6
// baseline (speedup 1.0000x reference)
#include <cuda_runtime.h>
#include <cuda_bf16.h>
#include <cstdint>

// ---------------------------------------------------------------------------
// ShapletLearner via bf16 mma.sync m16n8k16, 2-term split (hi+lo), 3 passes.
// R6: each pass gets its own accumulator set -> 6 independent 2-deep HMMA
// chains per warp (was 2 chains of 6) to keep the tensor pipe fed; zero-init
// via explicit-C (RZ) MMA form; running SMEM address registers.
// ---------------------------------------------------------------------------

constexpr int Bc = 2048;
constexpr int Qc = 1024;
constexpr int Kc = 32;
constexpr int Lc = 64;
constexpr int Sc = Qc - Kc + 1;   // 993

// D += A*B (accumulate into D)
#define MMAB(d0,d1,d2,d3, a0,a1,a2,a3, b0,b1) \
    asm("mma.sync.aligned.m16n8k16.row.col.f32.bf16.bf16.f32 " \
        "{%0,%1,%2,%3}, {%4,%5,%6,%7}, {%8,%9}, {%0,%1,%2,%3};" \
        : "+f"(d0), "+f"(d1), "+f"(d2), "+f"(d3) \
        : "r"(a0), "r"(a1), "r"(a2), "r"(a3), "r"(b0), "r"(b1))

// D = A*B (C = 0 -> RZ, no zero-MOVs, starts a fresh chain)
#define MMAZ(d0,d1,d2,d3, a0,a1,a2,a3, b0,b1) \
    asm("mma.sync.aligned.m16n8k16.row.col.f32.bf16.bf16.f32 " \
        "{%0,%1,%2,%3}, {%4,%5,%6,%7}, {%8,%9}, {%10,%11,%12,%13};" \
        : "=f"(d0), "=f"(d1), "=f"(d2), "=f"(d3) \
        : "r"(a0), "r"(a1), "r"(a2), "r"(a3), "r"(b0), "r"(b1), \
          "f"(0.f), "f"(0.f), "f"(0.f), "f"(0.f))

// k-chunk KC for both n-tiles, 3 passes into SEPARATE accumulators
#define KCH(MOP, O, KC) do { \
    enum { I0 = ((O) + 2*(KC)) % 6, I1 = ((O) + 2*(KC) + 1) % 6, \
           I2 = ((O) + 2*(KC) + 2) % 6 }; \
    MOP(h00,h01,h02,h03, rh[I0],rh[I1],rh[I1],rh[I2], Bh[0][KC][0], Bh[0][KC][1]); \
    MOP(u00,u01,u02,u03, rh[I0],rh[I1],rh[I1],rh[I2], Bl[0][KC][0], Bl[0][KC][1]); \
    MOP(v00,v01,v02,v03, rl[I0],rl[I1],rl[I1],rl[I2], Bh[0][KC][0], Bh[0][KC][1]); \
    MOP(h10,h11,h12,h13, rh[I0],rh[I1],rh[I1],rh[I2], Bh[1][KC][0], Bh[1][KC][1]); \
    MOP(u10,u11,u12,u13, rh[I0],rh[I1],rh[I1],rh[I2], Bl[1][KC][0], Bl[1][KC][1]); \
    MOP(v10,v11,v12,v13, rl[I0],rl[I1],rl[I1],rl[I2], Bh[1][KC][0], Bh[1][KC][1]); \
} while (0)

#define MERGE(MN, H, U, V, WQ) do { \
    float t_ = fmaf(H, -2.f, WQ); \
    t_ = fmaf(U, -2.f, t_); \
    t_ = fmaf(V, -2.f, t_); \
    MN = fminf(MN, t_); \
} while (0)

// one m16 tile at compile-time ring offset O; uses/advances running addrs
#define TILE(O) do { \
    float wq0_, wq1_; \
    asm("ld.shared.f32 %0, [%1];"      : "=f"(wq0_) : "r"(a_wq)); \
    asm("ld.shared.f32 %0, [%1+32];"   : "=f"(wq1_) : "r"(a_wq)); \
    float h00,h01,h02,h03,u00,u01,u02,u03,v00,v01,v02,v03; \
    float h10,h11,h12,h13,u10,u11,u12,u13,v10,v11,v12,v13; \
    KCH(MMAZ, O, 0); \
    KCH(MMAB, O, 1); \
    MERGE(mn00, h00, u00, v00, wq0_); \
    MERGE(mn01, h01, u01, v01, wq0_); \
    MERGE(mn02, h02, u02, v02, wq1_); \
    MERGE(mn03, h03, u03, v03, wq1_); \
    MERGE(mn10, h10, u10, v10, wq0_); \
    MERGE(mn11, h11, u11, v11, wq0_); \
    MERGE(mn12, h12, u12, v12, wq1_); \
    MERGE(mn13, h13, u13, v13, wq1_); \
    { enum { S5 = ((O) + 5) % 6, S6 = (O) % 6 }; \
      asm("ld.shared.b32 %0, [%1+160];" : "=r"(rh[S5]) : "r"(a_hi)); \
      asm("ld.shared.b32 %0, [%1+160];" : "=r"(rl[S5]) : "r"(a_lo)); \
      asm("ld.shared.b32 %0, [%1+192];" : "=r"(rh[S6]) : "r"(a_hi)); \
      asm("ld.shared.b32 %0, [%1+192];" : "=r"(rl[S6]) : "r"(a_lo)); } \
    a_wq += 64; a_hi += 64; a_lo += 64; \
} while (0)

static __device__ __forceinline__ uint32_t pack_bf16x2(float lo, float hi) {
    uint32_t r;
    asm("cvt.rn.bf16x2.f32 %0, %1, %2;" : "=r"(r) : "f"(hi), "f"(lo));
    return r;
}
static __device__ __forceinline__ uint32_t smem_u32(const void* p) {
    uint32_t a;
    asm("{ .reg .u64 t; cvta.to.shared.u64 t, %1; cvt.u32.u64 %0, t; }"
        : "=r"(a) : "l"(p));
    return a;
}

__global__ __launch_bounds__(128, 6) void shapelet_bmma(
    const float* __restrict__ ts,        // [B, Q]
    const float* __restrict__ shp,       // [L, K]
    const float* __restrict__ fc_w,      // [2, L]
    const float* __restrict__ fc_b,      // [2]
    float* __restrict__ out)             // [B, 2]
{
    __shared__ __align__(16) float    ts_sh[1152];    // fp32, zero-padded
    __shared__ __align__(16) uint32_t pair_hi[1120];  // (bf16 ts[i], ts[i+1])
    __shared__ __align__(16) uint32_t pair_lo[1120];  // residual pairs
    __shared__ __align__(16) float wsq_sh[1056];      // 1e38 guard s >= Sc
    __shared__ float ssq_sh[Lc];
    __shared__ float dsh[Lc];

    const int b    = blockIdx.x;
    const int tid  = threadIdx.x;
    const int w    = tid >> 5;
    const int lane = tid & 31;
    const int nrow = lane >> 2;
    const int kq   = lane & 3;

    // ---- stage ts + zero pad ----
    {
        const float4* src = reinterpret_cast<const float4*>(ts + (size_t)b * Qc);
        float4* dst = reinterpret_cast<float4*>(ts_sh);
        dst[tid]       = src[tid];
        dst[128 + tid] = src[128 + tid];
        if (tid < 32) dst[256 + tid] = make_float4(0.f, 0.f, 0.f, 0.f);
    }
    __syncthreads();

    // ---- packed bf16 hi/lo pair arrays ----
    #pragma unroll
    for (int i = tid; i < 1120; i += 128) {
        const float x0 = ts_sh[i], x1 = ts_sh[i + 1];
        const __nv_bfloat16 h0 = __float2bfloat16_rn(x0);
        const __nv_bfloat16 h1 = __float2bfloat16_rn(x1);
        pair_hi[i] = (uint32_t)__bfloat16_as_ushort(h0)
                   | ((uint32_t)__bfloat16_as_ushort(h1) << 16);
        pair_lo[i] = pack_bf16x2(x0 - __bfloat162float(h0),
                                 x1 - __bfloat162float(h1));
    }

    // ---- wsq[s] exact fp32 (incremental, 9 windows / thread) ----
    {
        const int sbase = tid * 9;
        if (sbase < 1056) {
            float ww = 0.f;
            #pragma unroll
            for (int k = 0; k < Kc; k++) {
                const float x = ts_sh[sbase + k];
                ww = fmaf(x, x, ww);
            }
            wsq_sh[sbase] = (sbase < Sc) ? ww : 1e38f;
            #pragma unroll
            for (int i = 1; i < 9; i++) {
                const int s = sbase + i;
                const float xo = ts_sh[s - 1], xn = ts_sh[s + 31];
                ww = ww - xo * xo + xn * xn;
                if (s < 1056) wsq_sh[s] = (s < Sc) ? ww : 1e38f;
            }
        }
    }

    // ---- ssq[l] exact fp32 ----
    if (tid < Lc) {
        float s = 0.f;
        #pragma unroll
        for (int k = 0; k < Kc; k++) {
            const float v = shp[tid * Kc + k];
            s = fmaf(v, v, s);
        }
        ssq_sh[tid] = s;
    }

    // ---- B fragments (hi/lo): warp covers n = w*16 .. w*16+15 ----
    uint32_t Bh[2][2][2], Bl[2][2][2];
    #pragma unroll
    for (int nt = 0; nt < 2; nt++)
        #pragma unroll
        for (int kc = 0; kc < 2; kc++)
            #pragma unroll
            for (int j = 0; j < 2; j++) {
                const int n = w * 16 + nt * 8 + nrow;
                const int k = 16 * kc + 8 * j + 2 * kq;
                const float x0 = shp[n * Kc + k];
                const float x1 = shp[n * Kc + k + 1];
                const __nv_bfloat16 h0 = __float2bfloat16_rn(x0);
                const __nv_bfloat16 h1 = __float2bfloat16_rn(x1);
                Bh[nt][kc][j] = (uint32_t)__bfloat16_as_ushort(h0)
                              | ((uint32_t)__bfloat16_as_ushort(h1) << 16);
                Bl[nt][kc][j] = pack_bf16x2(x0 - __bfloat162float(h0),
                                            x1 - __bfloat162float(h1));
            }
    __syncthreads();

    // ---- main loop: 66 m16 tiles, 6-slot pair ring, running addresses ----
    float mn00 = 3.4e38f, mn01 = 3.4e38f, mn02 = 3.4e38f, mn03 = 3.4e38f;
    float mn10 = 3.4e38f, mn11 = 3.4e38f, mn12 = 3.4e38f, mn13 = 3.4e38f;

    const int tb = nrow + 2 * kq;   // in [0,13]
    uint32_t rh[6], rl[6];
    #pragma unroll
    for (int m = 0; m < 5; m++) {
        rh[m] = pair_hi[tb + 8 * m];
        rl[m] = pair_lo[tb + 8 * m];
    }
    rh[5] = 0u; rl[5] = 0u;

    uint32_t a_wq = smem_u32(wsq_sh)  + (uint32_t)nrow * 4u;
    uint32_t a_hi = smem_u32(pair_hi) + (uint32_t)tb * 4u;
    uint32_t a_lo = smem_u32(pair_lo) + (uint32_t)tb * 4u;

    #pragma unroll 1
    for (int it = 0; it < 22; it++) {
        TILE(0);
        TILE(2);
        TILE(4);
    }

    // ---- reduce rows in-thread, then across row groups via shfl ----
    float m0 = fminf(mn00, mn02);
    float m1 = fminf(mn01, mn03);
    float m2 = fminf(mn10, mn12);
    float m3 = fminf(mn11, mn13);
    #pragma unroll
    for (int off = 4; off < 32; off <<= 1) {
        m0 = fminf(m0, __shfl_xor_sync(0xffffffffu, m0, off));
        m1 = fminf(m1, __shfl_xor_sync(0xffffffffu, m1, off));
        m2 = fminf(m2, __shfl_xor_sync(0xffffffffu, m2, off));
        m3 = fminf(m3, __shfl_xor_sync(0xffffffffu, m3, off));
    }
    if (nrow == 0) {
        const int n0 = w * 16 + 2 * kq;
        dsh[n0]     = (m0 + ssq_sh[n0])     * (1.0f / Kc);
        dsh[n0 + 1] = (m1 + ssq_sh[n0 + 1]) * (1.0f / Kc);
        dsh[n0 + 8] = (m2 + ssq_sh[n0 + 8]) * (1.0f / Kc);
        dsh[n0 + 9] = (m3 + ssq_sh[n0 + 9]) * (1.0f / Kc);
    }
    __syncthreads();

    // ---- FC epilogue ----
    if (tid < 2 * 32) {
        const int c = tid >> 5;
        const int l = tid & 31;
        float p = dsh[l] * fc_w[c * Lc + l]
                + dsh[l + 32] * fc_w[c * Lc + l + 32];
        #pragma unroll
        for (int off = 16; off > 0; off >>= 1)
            p += __shfl_down_sync(0xffffffffu, p, off);
        if (l == 0) out[b * 2 + c] = p + fc_b[c];
    }
}

extern "C" void kernel_launch(void* const* d_in, const int* in_sizes, int n_in,
                              void* d_out, int out_size)
{
    (void)in_sizes; (void)n_in; (void)out_size;
    const float* ts   = (const float*)d_in[0];
    const float* shp  = (const float*)d_in[1];
    const float* fc_w = (const float*)d_in[2];
    const float* fc_b = (const float*)d_in[3];
    float* out        = (float*)d_out;
    shapelet_bmma<<<Bc, 128>>>(ts, shp, fc_w, fc_b, out);
}

// round 7
// speedup vs baseline: 1.2355x; 1.2355x over previous
#include <cuda_runtime.h>
#include <cuda_bf16.h>
#include <cstdint>

// ---------------------------------------------------------------------------
// ShapletLearner via bf16 mma.sync m16n8k16, 2-term split (hi+lo), 3 passes:
//   cross = Hankel(ts) @ shp^T ~= ah*bh + ah*bl + al*bh  (drop al*bl ~2^-18)
//   dist = (wsq[s] - 2*cross + ssq[l])/K ; d[l]=min_s ; out = d@W^T + b
// R7 = R5 + separate accumulators per compensation pass (6 independent
// 2-deep HMMA chains/warp), explicit-C(0) MMA for zero-init, NO reg cap.
// ---------------------------------------------------------------------------

constexpr int Bc = 2048;
constexpr int Qc = 1024;
constexpr int Kc = 32;
constexpr int Lc = 64;
constexpr int Sc = Qc - Kc + 1;   // 993

// D += A*B
#define MMAB(d0,d1,d2,d3, a0,a1,a2,a3, b0,b1) \
    asm("mma.sync.aligned.m16n8k16.row.col.f32.bf16.bf16.f32 " \
        "{%0,%1,%2,%3}, {%4,%5,%6,%7}, {%8,%9}, {%0,%1,%2,%3};" \
        : "+f"(d0), "+f"(d1), "+f"(d2), "+f"(d3) \
        : "r"(a0), "r"(a1), "r"(a2), "r"(a3), "r"(b0), "r"(b1))

// D = A*B (C = 0, fresh chain, no zero-MOV dependency)
#define MMAZ(d0,d1,d2,d3, a0,a1,a2,a3, b0,b1) \
    asm("mma.sync.aligned.m16n8k16.row.col.f32.bf16.bf16.f32 " \
        "{%0,%1,%2,%3}, {%4,%5,%6,%7}, {%8,%9}, {%10,%11,%12,%13};" \
        : "=f"(d0), "=f"(d1), "=f"(d2), "=f"(d3) \
        : "r"(a0), "r"(a1), "r"(a2), "r"(a3), "r"(b0), "r"(b1), \
          "f"(0.f), "f"(0.f), "f"(0.f), "f"(0.f))

// k-chunk KC for both n-tiles; 3 passes into SEPARATE accumulator sets
#define KCH(MOP, O, KC) do { \
    enum { I0 = ((O) + 2*(KC)) % 6, I1 = ((O) + 2*(KC) + 1) % 6, \
           I2 = ((O) + 2*(KC) + 2) % 6 }; \
    MOP(h00,h01,h02,h03, rh[I0],rh[I1],rh[I1],rh[I2], Bh[0][KC][0], Bh[0][KC][1]); \
    MOP(u00,u01,u02,u03, rh[I0],rh[I1],rh[I1],rh[I2], Bl[0][KC][0], Bl[0][KC][1]); \
    MOP(v00,v01,v02,v03, rl[I0],rl[I1],rl[I1],rl[I2], Bh[0][KC][0], Bh[0][KC][1]); \
    MOP(h10,h11,h12,h13, rh[I0],rh[I1],rh[I1],rh[I2], Bh[1][KC][0], Bh[1][KC][1]); \
    MOP(u10,u11,u12,u13, rh[I0],rh[I1],rh[I1],rh[I2], Bl[1][KC][0], Bl[1][KC][1]); \
    MOP(v10,v11,v12,v13, rl[I0],rl[I1],rl[I1],rl[I2], Bh[1][KC][0], Bh[1][KC][1]); \
} while (0)

#define MERGE(MN, H, U, V, WQ) do { \
    float t_ = fmaf(H, -2.f, WQ); \
    t_ = fmaf(U, -2.f, t_); \
    t_ = fmaf(V, -2.f, t_); \
    MN = fminf(MN, t_); \
} while (0)

// one m16 tile: ring offset O = (2*TT)%6 (compile-time), tile index TT
#define TILE(O, TT) do { \
    const int s0_ = (TT) << 4; \
    const float wq0_ = wsq_sh[s0_ + nrow]; \
    const float wq1_ = wsq_sh[s0_ + nrow + 8]; \
    float h00,h01,h02,h03,u00,u01,u02,u03,v00,v01,v02,v03; \
    float h10,h11,h12,h13,u10,u11,u12,u13,v10,v11,v12,v13; \
    KCH(MMAZ, O, 0); \
    KCH(MMAB, O, 1); \
    MERGE(mn00, h00, u00, v00, wq0_); \
    MERGE(mn01, h01, u01, v01, wq0_); \
    MERGE(mn02, h02, u02, v02, wq1_); \
    MERGE(mn03, h03, u03, v03, wq1_); \
    MERGE(mn10, h10, u10, v10, wq0_); \
    MERGE(mn11, h11, u11, v11, wq0_); \
    MERGE(mn12, h12, u12, v12, wq1_); \
    MERGE(mn13, h13, u13, v13, wq1_); \
    { enum { S5 = ((O) + 5) % 6, S6 = (O) % 6 };  /* m=2t+5, m=2t+6 */ \
      const int gi_ = s0_ + tb; \
      rh[S5] = pair_hi[gi_ + 40];  rl[S5] = pair_lo[gi_ + 40]; \
      rh[S6] = pair_hi[gi_ + 48];  rl[S6] = pair_lo[gi_ + 48]; } \
} while (0)

static __device__ __forceinline__ uint32_t pack_bf16x2(float lo, float hi) {
    uint32_t r;
    asm("cvt.rn.bf16x2.f32 %0, %1, %2;" : "=r"(r) : "f"(hi), "f"(lo));
    return r;
}

__global__ __launch_bounds__(128) void shapelet_bmma(
    const float* __restrict__ ts,        // [B, Q]
    const float* __restrict__ shp,       // [L, K]
    const float* __restrict__ fc_w,      // [2, L]
    const float* __restrict__ fc_b,      // [2]
    float* __restrict__ out)             // [B, 2]
{
    __shared__ __align__(16) float    ts_sh[1152];    // fp32, zero-padded
    __shared__ __align__(16) uint32_t pair_hi[1120];  // (bf16 ts[i], ts[i+1])
    __shared__ __align__(16) uint32_t pair_lo[1120];  // residual pairs
    __shared__ __align__(16) float wsq_sh[1056];      // 1e38 guard s >= Sc
    __shared__ float ssq_sh[Lc];
    __shared__ float dsh[Lc];

    const int b    = blockIdx.x;
    const int tid  = threadIdx.x;
    const int w    = tid >> 5;
    const int lane = tid & 31;
    const int nrow = lane >> 2;
    const int kq   = lane & 3;

    // ---- stage ts + zero pad to 1152 ----
    {
        const float4* src = reinterpret_cast<const float4*>(ts + (size_t)b * Qc);
        float4* dst = reinterpret_cast<float4*>(ts_sh);
        dst[tid]       = src[tid];
        dst[128 + tid] = src[128 + tid];
        if (tid < 32) dst[256 + tid] = make_float4(0.f, 0.f, 0.f, 0.f);
    }
    __syncthreads();

    // ---- packed bf16 hi/lo pair arrays ----
    #pragma unroll
    for (int i = tid; i < 1120; i += 128) {
        const float x0 = ts_sh[i], x1 = ts_sh[i + 1];
        const __nv_bfloat16 h0 = __float2bfloat16_rn(x0);
        const __nv_bfloat16 h1 = __float2bfloat16_rn(x1);
        pair_hi[i] = (uint32_t)__bfloat16_as_ushort(h0)
                   | ((uint32_t)__bfloat16_as_ushort(h1) << 16);
        pair_lo[i] = pack_bf16x2(x0 - __bfloat162float(h0),
                                 x1 - __bfloat162float(h1));
    }

    // ---- wsq[s] exact fp32 (incremental, 9 windows / thread) ----
    {
        const int sbase = tid * 9;
        if (sbase < 1056) {
            float ww = 0.f;
            #pragma unroll
            for (int k = 0; k < Kc; k++) {
                const float x = ts_sh[sbase + k];
                ww = fmaf(x, x, ww);
            }
            wsq_sh[sbase] = (sbase < Sc) ? ww : 1e38f;
            #pragma unroll
            for (int i = 1; i < 9; i++) {
                const int s = sbase + i;
                const float xo = ts_sh[s - 1], xn = ts_sh[s + 31];
                ww = ww - xo * xo + xn * xn;
                if (s < 1056) wsq_sh[s] = (s < Sc) ? ww : 1e38f;
            }
        }
    }

    // ---- ssq[l] exact fp32 ----
    if (tid < Lc) {
        float s = 0.f;
        #pragma unroll
        for (int k = 0; k < Kc; k++) {
            const float v = shp[tid * Kc + k];
            s = fmaf(v, v, s);
        }
        ssq_sh[tid] = s;
    }

    // ---- B fragments (hi/lo): warp covers n = w*16 .. w*16+15 ----
    uint32_t Bh[2][2][2], Bl[2][2][2];
    #pragma unroll
    for (int nt = 0; nt < 2; nt++)
        #pragma unroll
        for (int kc = 0; kc < 2; kc++)
            #pragma unroll
            for (int j = 0; j < 2; j++) {
                const int n = w * 16 + nt * 8 + nrow;
                const int k = 16 * kc + 8 * j + 2 * kq;
                const float x0 = shp[n * Kc + k];
                const float x1 = shp[n * Kc + k + 1];
                const __nv_bfloat16 h0 = __float2bfloat16_rn(x0);
                const __nv_bfloat16 h1 = __float2bfloat16_rn(x1);
                Bh[nt][kc][j] = (uint32_t)__bfloat16_as_ushort(h0)
                              | ((uint32_t)__bfloat16_as_ushort(h1) << 16);
                Bl[nt][kc][j] = pack_bf16x2(x0 - __bfloat162float(h0),
                                            x1 - __bfloat162float(h1));
            }
    __syncthreads();

    // ---- main loop: 66 m16 tiles, 6-slot pair ring ----
    float mn00 = 3.4e38f, mn01 = 3.4e38f, mn02 = 3.4e38f, mn03 = 3.4e38f;
    float mn10 = 3.4e38f, mn11 = 3.4e38f, mn12 = 3.4e38f, mn13 = 3.4e38f;

    const int tb = nrow + 2 * kq;   // in [0,13]
    uint32_t rh[6], rl[6];
    #pragma unroll
    for (int m = 0; m < 5; m++) {
        rh[m] = pair_hi[tb + 8 * m];
        rl[m] = pair_lo[tb + 8 * m];
    }
    rh[5] = 0u; rl[5] = 0u;

    #pragma unroll 1
    for (int it = 0; it < 22; it++) {
        const int t3 = it * 3;
        TILE(0, t3);
        TILE(2, t3 + 1);
        TILE(4, t3 + 2);
    }

    // ---- reduce rows in-thread, then across row groups via shfl ----
    float m0 = fminf(mn00, mn02);
    float m1 = fminf(mn01, mn03);
    float m2 = fminf(mn10, mn12);
    float m3 = fminf(mn11, mn13);
    #pragma unroll
    for (int off = 4; off < 32; off <<= 1) {
        m0 = fminf(m0, __shfl_xor_sync(0xffffffffu, m0, off));
        m1 = fminf(m1, __shfl_xor_sync(0xffffffffu, m1, off));
        m2 = fminf(m2, __shfl_xor_sync(0xffffffffu, m2, off));
        m3 = fminf(m3, __shfl_xor_sync(0xffffffffu, m3, off));
    }
    if (nrow == 0) {
        const int n0 = w * 16 + 2 * kq;
        dsh[n0]     = (m0 + ssq_sh[n0])     * (1.0f / Kc);
        dsh[n0 + 1] = (m1 + ssq_sh[n0 + 1]) * (1.0f / Kc);
        dsh[n0 + 8] = (m2 + ssq_sh[n0 + 8]) * (1.0f / Kc);
        dsh[n0 + 9] = (m3 + ssq_sh[n0 + 9]) * (1.0f / Kc);
    }
    __syncthreads();

    // ---- FC epilogue ----
    if (tid < 2 * 32) {
        const int c = tid >> 5;
        const int l = tid & 31;
        float p = dsh[l] * fc_w[c * Lc + l]
                + dsh[l + 32] * fc_w[c * Lc + l + 32];
        #pragma unroll
        for (int off = 16; off > 0; off >>= 1)
            p += __shfl_down_sync(0xffffffffu, p, off);
        if (l == 0) out[b * 2 + c] = p + fc_b[c];
    }
}

extern "C" void kernel_launch(void* const* d_in, const int* in_sizes, int n_in,
                              void* d_out, int out_size)
{
    (void)in_sizes; (void)n_in; (void)out_size;
    const float* ts   = (const float*)d_in[0];
    const float* shp  = (const float*)d_in[1];
    const float* fc_w = (const float*)d_in[2];
    const float* fc_b = (const float*)d_in[3];
    float* out        = (float*)d_out;
    shapelet_bmma<<<Bc, 128>>>(ts, shp, fc_w, fc_b, out);
}